// round 1
// baseline (speedup 1.0000x reference)
#include <cuda_runtime.h>
#include <cuda_bf16.h>
#include <math.h>
#include <math_constants.h>

// ---------------- static geometry constants ----------------
#define HB 512
#define WB 512
#define NB (HB*WB)          // 262144 BEV cells
#define NC 64               // channels
#define NBATCH 2
#define HR 64
#define WR 2048

// device scratch (static __device__ arrays: allowed workaround for no-alloc rule)
__device__ float          g_rho[NB];
__device__ unsigned short g_colb[NB];
__device__ unsigned char  g_rowlow[NB];
__device__ unsigned short g_range[NBATCH * NB];   // rs | re<<8 per (b,cell)
__device__ int            g_cnt[WR];
__device__ int            g_off[WR + 1];
__device__ int            g_cursor[WR];
__device__ int            g_list[NB];
__device__ float          g_featT[(size_t)NBATCH * NB * NC];        // [B][N][C]  134MB
__device__ float          g_scratch[(size_t)NBATCH * WR * HR * NC]; // [B][col][r][c] 67MB

// geometry constants, matching python double math then f32 casts
__device__ __forceinline__ float th_maxf()   { return (float)(3.0 * (CUDART_PI / 180.0)); }
__device__ __forceinline__ float th_rangef() {
    double tmax = 3.0 * (CUDART_PI / 180.0);
    double tmin = -25.0 * (CUDART_PI / 180.0);
    return (float)(tmax - tmin);
}
__device__ __forceinline__ float phi_minf()   { return (float)(-CUDART_PI); }
__device__ __forceinline__ float phi_rangef() { return (float)(2.0 * CUDART_PI); }

__device__ __forceinline__ int row_from_theta(float theta) {
    float v = __fmul_rn(__fdiv_rn(__fsub_rn(th_maxf(), theta), th_rangef()), 63.0f);
    v = rintf(v);                       // round half-even, like np/jnp round
    v = fminf(fmaxf(v, 0.0f), 63.0f);
    return (int)v;
}

// ---------------- kernels ----------------
__global__ void k_zero() {
    int t = blockIdx.x * blockDim.x + threadIdx.x;
    if (t < WR) g_cnt[t] = 0;
}

__global__ void k_geom() {
    int n = blockIdx.x * blockDim.x + threadIdx.x;
    if (n >= NB) return;
    int i = n >> 9;          // y index
    int j = n & 511;         // x index
    // np.linspace semantics: ((i*delta)/div)+start in double, then f32 cast
    float y = (float)(((double)i * (-100.0)) / 511.0 + 50.0);
    float x = (float)(((double)j * (100.0)) / 511.0 + (-50.0));
    float rho = __fsqrt_rn(__fadd_rn(__fmul_rn(x, x), __fmul_rn(y, y)));
    float phi = atan2f(y, x);
    float theta_low = atan2f(-1.73f, rho);

    int row_low = row_from_theta(theta_low);

    float cv = __fmul_rn(__fdiv_rn(__fsub_rn(phi, phi_minf()), phi_rangef()), 2047.0f);
    cv = rintf(cv);
    cv = fminf(fmaxf(cv, 0.0f), 2047.0f);
    int col = (int)cv;

    g_rho[n]    = rho;
    g_rowlow[n] = (unsigned char)row_low;
    g_colb[n]   = (unsigned short)col;
    atomicAdd(&g_cnt[col], 1);
}

__global__ void k_scan() {
    __shared__ int s[WR];
    int t = threadIdx.x;                 // 1024 threads, 2 elems each
    s[t]        = g_cnt[t];
    s[t + 1024] = g_cnt[t + 1024];
    __syncthreads();
    for (int off = 1; off < WR; off <<= 1) {
        int a  = (t >= off)        ? s[t - off]        : 0;
        int b2 = (t + 1024 >= off) ? s[t + 1024 - off] : 0;
        __syncthreads();
        s[t]        += a;
        s[t + 1024] += b2;
        __syncthreads();
    }
    if (t == 0) g_off[0] = 0;
    g_off[t + 1]    = s[t];
    g_off[t + 1025] = s[t + 1024];
    g_cursor[t]        = (t == 0) ? 0 : s[t - 1];
    g_cursor[t + 1024] = s[t + 1023];
}

__global__ void k_fill() {
    int n = blockIdx.x * blockDim.x + threadIdx.x;
    if (n >= NB) return;
    int col = g_colb[n];
    int pos = atomicAdd(&g_cursor[col], 1);
    g_list[pos] = n;
}

__global__ void k_rowhi(const int* __restrict__ zbin) {
    int idx = blockIdx.x * blockDim.x + threadIdx.x;
    if (idx >= NBATCH * NB) return;
    int n = idx & (NB - 1);
    int zb = zbin[idx];
    // z_hint = z*DZ + (Z_MIN + DZ/2), f32 mul then add (no fma contraction)
    float zh = __fadd_rn(__fmul_rn((float)zb, (float)(6.0 / 30.0)),
                         (float)(-4.0 + (6.0 / 30.0) / 2.0));
    float theta_hi = atan2f(zh, g_rho[n]);
    int row_hi  = row_from_theta(theta_hi);
    int row_low = (int)g_rowlow[n];
    int rs = min(row_low, row_hi);
    int re = max(row_low, row_hi);
    g_range[idx] = (unsigned short)(rs | (re << 8));
}

// [B,C,N] -> [B,N,C]
__global__ void k_transpose(const float* __restrict__ src) {
    __shared__ float tile[32][33];
    int b  = blockIdx.z;
    int n0 = blockIdx.x * 32;
    int c0 = blockIdx.y * 32;
    int tx = threadIdx.x, ty = threadIdx.y;
    #pragma unroll
    for (int i = 0; i < 32; i += 8) {
        tile[ty + i][tx] = src[((size_t)(b * NC + c0 + ty + i)) * NB + n0 + tx];
    }
    __syncthreads();
    #pragma unroll
    for (int i = 0; i < 32; i += 8) {
        g_featT[((size_t)b * NB + (n0 + ty + i)) * NC + c0 + tx] = tile[tx][ty + i];
    }
}

// CTA = (col, b). 64 threads = 64 channels. smem acc[r][c].
__global__ void __launch_bounds__(64) k_project() {
    __shared__ float acc[HR * NC];   // 16KB
    int col = blockIdx.x;
    int b   = blockIdx.y;
    int c   = threadIdx.x;           // 0..63

    #pragma unroll
    for (int r = 0; r < HR; ++r) acc[r * NC + c] = -CUDART_INF_F;
    __syncthreads();   // (not strictly needed: each thread only touches its own channel)

    int start = g_off[col];
    int end   = g_off[col + 1];
    const float* featT = g_featT + ((size_t)b * NB) * NC;
    const unsigned short* rng_base = g_range + (size_t)b * NB;

    for (int i = start; i < end; ++i) {
        int cell = g_list[i];                         // broadcast
        float v  = featT[((size_t)cell << 6) + c];    // coalesced 256B
        unsigned rng = rng_base[cell];                // broadcast
        int rs = rng & 255;
        int re = rng >> 8;
        float* p = acc + rs * NC + c;
        int span = re - rs + 1;
        #pragma unroll 4
        for (int k = 0; k < span; ++k) {
            *p = fmaxf(*p, v);
            p += NC;
        }
    }
    __syncthreads();

    float* dst = g_scratch + (((size_t)(b * WR + col)) << 12);  // *HR*NC
    #pragma unroll
    for (int r = 0; r < HR; ++r) dst[r * NC + c] = acc[r * NC + c];
}

// scratch [b][col][r][c] -> out [b][c][r][col], -inf -> 0
__global__ void k_final(float* __restrict__ out) {
    __shared__ float tile[32][33];
    int z = blockIdx.z;
    int b = z >> 6;
    int r = z & 63;
    int col0 = blockIdx.x * 32;
    int c0   = blockIdx.y * 32;
    int tx = threadIdx.x, ty = threadIdx.y;
    #pragma unroll
    for (int i = 0; i < 32; i += 8) {
        tile[ty + i][tx] =
            g_scratch[(((size_t)(b * WR + col0 + ty + i)) << 12) + (r << 6) + c0 + tx];
    }
    __syncthreads();
    #pragma unroll
    for (int i = 0; i < 32; i += 8) {
        float v = tile[tx][ty + i];
        if (v == -CUDART_INF_F) v = 0.0f;
        out[(((size_t)(b * NC + c0 + ty + i)) * HR + r) * WR + col0 + tx] = v;
    }
}

extern "C" void kernel_launch(void* const* d_in, const int* in_sizes, int n_in,
                              void* d_out, int out_size) {
    const float* feat = (const float*)d_in[0];   // [2,64,512,512] f32
    const int*   zbin = (const int*)d_in[1];     // [2,1,512,512] i32
    float*       out  = (float*)d_out;           // [2,64,64,2048] f32

    k_zero<<<(WR + 255) / 256, 256>>>();
    k_geom<<<NB / 256, 256>>>();
    k_scan<<<1, 1024>>>();
    k_fill<<<NB / 256, 256>>>();
    k_rowhi<<<(NBATCH * NB) / 256, 256>>>(zbin);
    k_transpose<<<dim3(NB / 32, NC / 32, NBATCH), dim3(32, 8)>>>(feat);
    k_project<<<dim3(WR, NBATCH), 64>>>();
    k_final<<<dim3(WR / 32, NC / 32, NBATCH * HR), dim3(32, 8)>>>(out);
}

// round 2
// speedup vs baseline: 1.4485x; 1.4485x over previous
#include <cuda_runtime.h>
#include <cuda_bf16.h>
#include <math.h>
#include <math_constants.h>

#define HB 512
#define WB 512
#define NB (HB*WB)          // 262144 BEV cells
#define NC 64               // channels
#define NBATCH 2
#define HR 64
#define WR 2048
#define CAP 512             // bucket capacity per column (max observed ~210)
#define SLOTS (WR*CAP)

// device scratch
__device__ float          g_rho[NB];
__device__ unsigned char  g_rowlow[NB];
__device__ int            g_slot[NB];
__device__ int            g_cnt[WR];
__device__ unsigned int   g_item[(size_t)NBATCH * SLOTS];           // (cell<<12)|(rs<<6)|re
__device__ float          g_featT[(size_t)NBATCH * NB * NC];        // [B][N][C]
__device__ float          g_scratch[(size_t)NBATCH * WR * HR * NC]; // [B][col][r][c]

__device__ __forceinline__ float th_maxf()   { return (float)(3.0 * (CUDART_PI / 180.0)); }
__device__ __forceinline__ float th_rangef() {
    double tmax = 3.0 * (CUDART_PI / 180.0);
    double tmin = -25.0 * (CUDART_PI / 180.0);
    return (float)(tmax - tmin);
}
__device__ __forceinline__ float phi_minf()   { return (float)(-CUDART_PI); }
__device__ __forceinline__ float phi_rangef() { return (float)(2.0 * CUDART_PI); }

__device__ __forceinline__ int row_from_theta(float theta) {
    float v = __fmul_rn(__fdiv_rn(__fsub_rn(th_maxf(), theta), th_rangef()), 63.0f);
    v = rintf(v);
    v = fminf(fmaxf(v, 0.0f), 63.0f);
    return (int)v;
}

// ---------------- kernels ----------------
__global__ void k_zero() {
    int t = blockIdx.x * blockDim.x + threadIdx.x;
    if (t < WR) g_cnt[t] = 0;
}

__global__ void k_geom() {
    int n = blockIdx.x * blockDim.x + threadIdx.x;
    if (n >= NB) return;
    int i = n >> 9;
    int j = n & 511;
    float y = (float)(((double)i * (-100.0)) / 511.0 + 50.0);
    float x = (float)(((double)j * (100.0)) / 511.0 + (-50.0));
    float rho = __fsqrt_rn(__fadd_rn(__fmul_rn(x, x), __fmul_rn(y, y)));
    float phi = atan2f(y, x);
    float theta_low = atan2f(-1.73f, rho);

    int row_low = row_from_theta(theta_low);

    float cv = __fmul_rn(__fdiv_rn(__fsub_rn(phi, phi_minf()), phi_rangef()), 2047.0f);
    cv = rintf(cv);
    cv = fminf(fmaxf(cv, 0.0f), 2047.0f);
    int col = (int)cv;

    int pos = atomicAdd(&g_cnt[col], 1);

    g_rho[n]    = rho;
    g_rowlow[n] = (unsigned char)row_low;
    g_slot[n]   = col * CAP + pos;
}

__global__ void k_rowhi(const int* __restrict__ zbin) {
    int idx = blockIdx.x * blockDim.x + threadIdx.x;
    if (idx >= NBATCH * NB) return;
    int n = idx & (NB - 1);
    int b = idx >> 18;
    int zb = zbin[idx];
    float zh = __fadd_rn(__fmul_rn((float)zb, (float)(6.0 / 30.0)),
                         (float)(-4.0 + (6.0 / 30.0) / 2.0));
    float theta_hi = atan2f(zh, g_rho[n]);
    int row_hi  = row_from_theta(theta_hi);
    int row_low = (int)g_rowlow[n];
    int rs = min(row_low, row_hi);
    int re = max(row_low, row_hi);
    g_item[(size_t)b * SLOTS + g_slot[n]] =
        ((unsigned)n << 12) | ((unsigned)rs << 6) | (unsigned)re;
}

// [B,C,N] -> [B,N,C]
__global__ void k_transpose(const float* __restrict__ src) {
    __shared__ float tile[32][33];
    int b  = blockIdx.z;
    int n0 = blockIdx.x * 32;
    int c0 = blockIdx.y * 32;
    int tx = threadIdx.x, ty = threadIdx.y;
    #pragma unroll
    for (int i = 0; i < 32; i += 8) {
        tile[ty + i][tx] = src[((size_t)(b * NC + c0 + ty + i)) * NB + n0 + tx];
    }
    __syncthreads();
    #pragma unroll
    for (int i = 0; i < 32; i += 8) {
        g_featT[((size_t)b * NB + (n0 + ty + i)) * NC + c0 + tx] = tile[tx][ty + i];
    }
}

// CTA = (col, b). 256 threads = 8 row-groups x 32 lanes (float2 channels).
__global__ void __launch_bounds__(256) k_project() {
    __shared__ float acc[HR * NC];          // 16KB
    __shared__ unsigned items[CAP];
    int col = blockIdx.x;
    int b   = blockIdx.y;
    int t    = threadIdx.x;
    int g    = t >> 5;                      // row group, rows [8g, 8g+8)
    int lane = t & 31;                      // channels 2*lane, 2*lane+1
    int glo = g * 8, ghi = glo + 7;

    float2* acc2 = (float2*)acc;

    // init own rows
    #pragma unroll
    for (int r = 0; r < 8; ++r)
        acc2[(glo + r) * 32 + lane] = make_float2(-CUDART_INF_F, -CUDART_INF_F);

    int cnt = g_cnt[col];
    const unsigned* src_items = g_item + (size_t)b * SLOTS + col * CAP;
    for (int i = t; i < cnt; i += 256) items[i] = src_items[i];
    __syncthreads();

    const float2* featT2 = (const float2*)(g_featT + ((size_t)b * NB) * NC);

    for (int i = 0; i < cnt; ++i) {
        unsigned it = items[i];
        int re = it & 63;
        int rs = (it >> 6) & 63;
        int lo = max(rs, glo);
        int hi = min(re, ghi);
        if (lo > hi) continue;              // warp-uniform branch
        int cell = it >> 12;
        float2 v = __ldg(&featT2[((size_t)cell << 5) + lane]);
        float2* p = acc2 + lo * 32 + lane;
        #pragma unroll 2
        for (int r = lo; r <= hi; ++r) {
            float2 a = *p;
            a.x = fmaxf(a.x, v.x);
            a.y = fmaxf(a.y, v.y);
            *p = a;
            p += 32;
        }
    }
    // no sync needed: each warp only touches its own rows

    float2* dst2 = (float2*)(g_scratch + (((size_t)(b * WR + col)) << 12));
    #pragma unroll
    for (int r = 0; r < 8; ++r)
        dst2[(glo + r) * 32 + lane] = acc2[(glo + r) * 32 + lane];
}

// scratch [b][col][r][c] -> out [b][c][r][col], -inf -> 0
__global__ void k_final(float* __restrict__ out) {
    __shared__ float tile[32][33];
    int z = blockIdx.z;
    int b = z >> 6;
    int r = z & 63;
    int col0 = blockIdx.x * 32;
    int c0   = blockIdx.y * 32;
    int tx = threadIdx.x, ty = threadIdx.y;
    #pragma unroll
    for (int i = 0; i < 32; i += 8) {
        tile[ty + i][tx] =
            g_scratch[(((size_t)(b * WR + col0 + ty + i)) << 12) + (r << 6) + c0 + tx];
    }
    __syncthreads();
    #pragma unroll
    for (int i = 0; i < 32; i += 8) {
        float v = tile[tx][ty + i];
        if (v == -CUDART_INF_F) v = 0.0f;
        out[(((size_t)(b * NC + c0 + ty + i)) * HR + r) * WR + col0 + tx] = v;
    }
}

extern "C" void kernel_launch(void* const* d_in, const int* in_sizes, int n_in,
                              void* d_out, int out_size) {
    const float* feat = (const float*)d_in[0];   // [2,64,512,512] f32
    const int*   zbin = (const int*)d_in[1];     // [2,1,512,512] i32
    float*       out  = (float*)d_out;           // [2,64,64,2048] f32

    k_zero<<<(WR + 255) / 256, 256>>>();
    k_geom<<<NB / 256, 256>>>();
    k_rowhi<<<(NBATCH * NB) / 256, 256>>>(zbin);
    k_transpose<<<dim3(NB / 32, NC / 32, NBATCH), dim3(32, 8)>>>(feat);
    k_project<<<dim3(WR, NBATCH), 256>>>();
    k_final<<<dim3(WR / 32, NC / 32, NBATCH * HR), dim3(32, 8)>>>(out);
}

// round 3
// speedup vs baseline: 1.7145x; 1.1836x over previous
#include <cuda_runtime.h>
#include <cuda_bf16.h>
#include <math.h>
#include <math_constants.h>

#define HB 512
#define WB 512
#define NB (HB*WB)          // 262144 BEV cells
#define NC 64               // channels
#define NBATCH 2
#define HR 64
#define WR 2048
#define NG 8                // row groups (8 rows each)
#define CAP2 512            // bucket capacity per (col,group)

// device scratch
__device__ float          g_rho[NB];
__device__ unsigned char  g_rowlow[NB];
__device__ unsigned short g_colb[NB];
__device__ int            g_cnt2[NBATCH * WR * NG];
__device__ unsigned int   g_item[(size_t)NBATCH * WR * NG * CAP2]; // (cell<<6)|(lo<<3)|hi
__device__ float          g_featT[(size_t)NBATCH * NB * NC];        // [B][N][C]
__device__ float          g_scratch[(size_t)NBATCH * WR * HR * NC]; // [B][col][r][c]

__device__ __forceinline__ float th_maxf()   { return (float)(3.0 * (CUDART_PI / 180.0)); }
__device__ __forceinline__ float th_rangef() {
    double tmax = 3.0 * (CUDART_PI / 180.0);
    double tmin = -25.0 * (CUDART_PI / 180.0);
    return (float)(tmax - tmin);
}
__device__ __forceinline__ float phi_minf()   { return (float)(-CUDART_PI); }
__device__ __forceinline__ float phi_rangef() { return (float)(2.0 * CUDART_PI); }

__device__ __forceinline__ int row_from_theta(float theta) {
    float v = __fmul_rn(__fdiv_rn(__fsub_rn(th_maxf(), theta), th_rangef()), 63.0f);
    v = rintf(v);
    v = fminf(fmaxf(v, 0.0f), 63.0f);
    return (int)v;
}

// ---------------- kernels ----------------
__global__ void k_zero() {
    int t = blockIdx.x * blockDim.x + threadIdx.x;
    if (t < NBATCH * WR * NG) g_cnt2[t] = 0;
}

__global__ void k_geom() {
    int n = blockIdx.x * blockDim.x + threadIdx.x;
    if (n >= NB) return;
    int i = n >> 9;
    int j = n & 511;
    float y = (float)(((double)i * (-100.0)) / 511.0 + 50.0);
    float x = (float)(((double)j * (100.0)) / 511.0 + (-50.0));
    float rho = __fsqrt_rn(__fadd_rn(__fmul_rn(x, x), __fmul_rn(y, y)));
    float phi = atan2f(y, x);
    float theta_low = atan2f(-1.73f, rho);

    int row_low = row_from_theta(theta_low);

    float cv = __fmul_rn(__fdiv_rn(__fsub_rn(phi, phi_minf()), phi_rangef()), 2047.0f);
    cv = rintf(cv);
    cv = fminf(fmaxf(cv, 0.0f), 2047.0f);
    int col = (int)cv;

    g_rho[n]    = rho;
    g_rowlow[n] = (unsigned char)row_low;
    g_colb[n]   = (unsigned short)col;
}

// per (b,cell): compute [rs,re], scatter into intersecting (col,row-group) buckets
__global__ void k_rowhi(const int* __restrict__ zbin) {
    int idx = blockIdx.x * blockDim.x + threadIdx.x;
    if (idx >= NBATCH * NB) return;
    int n = idx & (NB - 1);
    int b = idx >> 18;
    int zb = zbin[idx];
    float zh = __fadd_rn(__fmul_rn((float)zb, (float)(6.0 / 30.0)),
                         (float)(-4.0 + (6.0 / 30.0) / 2.0));
    float theta_hi = atan2f(zh, g_rho[n]);
    int row_hi  = row_from_theta(theta_hi);
    int row_low = (int)g_rowlow[n];
    int rs = min(row_low, row_hi);
    int re = max(row_low, row_hi);
    int col  = (int)g_colb[n];
    int base = (b * WR + col) * NG;
    int g0 = rs >> 3, g1 = re >> 3;
    for (int g = g0; g <= g1; ++g) {
        int lo = max(rs - g * 8, 0);
        int hi = min(re - g * 8, 7);
        int pos = atomicAdd(&g_cnt2[base + g], 1);
        if (pos < CAP2)
            g_item[(size_t)(base + g) * CAP2 + pos] =
                ((unsigned)n << 6) | ((unsigned)lo << 3) | (unsigned)hi;
    }
}

// [B,C,N] -> [B,N,C], both sides 128-bit
__global__ void k_transpose(const float* __restrict__ src) {
    __shared__ float tile[32][33];
    int b  = blockIdx.z;
    int n0 = blockIdx.x * 32;
    int c0 = blockIdx.y * 32;
    int tx = threadIdx.x;   // 0..7
    int ty = threadIdx.y;   // 0..31
    float4 f = *(const float4*)&src[((size_t)(b * NC + c0 + ty)) * NB + n0 + tx * 4];
    tile[tx * 4 + 0][ty] = f.x;
    tile[tx * 4 + 1][ty] = f.y;
    tile[tx * 4 + 2][ty] = f.z;
    tile[tx * 4 + 3][ty] = f.w;
    __syncthreads();
    float4 w;
    w.x = tile[ty][tx * 4 + 0];
    w.y = tile[ty][tx * 4 + 1];
    w.z = tile[ty][tx * 4 + 2];
    w.w = tile[ty][tx * 4 + 3];
    *(float4*)&g_featT[((size_t)b * NB + (n0 + ty)) * NC + c0 + tx * 4] = w;
}

// CTA = (col, b). 8 warps = 8 row groups; lane owns 2 channels; acc in registers.
__global__ void __launch_bounds__(256) k_project() {
    int col = blockIdx.x;
    int b   = blockIdx.y;
    int t    = threadIdx.x;
    int g    = t >> 5;
    int lane = t & 31;

    float2 a0 = make_float2(-CUDART_INF_F, -CUDART_INF_F);
    float2 a1 = a0, a2 = a0, a3 = a0, a4 = a0, a5 = a0, a6 = a0, a7 = a0;

    int base = (b * WR + col) * NG + g;
    int cnt  = min(g_cnt2[base], CAP2);
    const unsigned* items = g_item + (size_t)base * CAP2;
    const float2* featT2  = (const float2*)g_featT + (size_t)b * NB * 32;

    unsigned it = (cnt > 0) ? items[0] : 0u;
    for (int i = 0; i < cnt; ++i) {
        unsigned nx = (i + 1 < cnt) ? items[i + 1] : 0u;
        int cell = it >> 6;
        int lo = (it >> 3) & 7;
        int hi = it & 7;
        float2 v = __ldg(&featT2[((size_t)cell << 5) + lane]);
        float nf = -CUDART_INF_F;
        float vx0 = (0 >= lo && 0 <= hi) ? v.x : nf, vy0 = (0 >= lo && 0 <= hi) ? v.y : nf;
        float vx1 = (1 >= lo && 1 <= hi) ? v.x : nf, vy1 = (1 >= lo && 1 <= hi) ? v.y : nf;
        float vx2 = (2 >= lo && 2 <= hi) ? v.x : nf, vy2 = (2 >= lo && 2 <= hi) ? v.y : nf;
        float vx3 = (3 >= lo && 3 <= hi) ? v.x : nf, vy3 = (3 >= lo && 3 <= hi) ? v.y : nf;
        float vx4 = (4 >= lo && 4 <= hi) ? v.x : nf, vy4 = (4 >= lo && 4 <= hi) ? v.y : nf;
        float vx5 = (5 >= lo && 5 <= hi) ? v.x : nf, vy5 = (5 >= lo && 5 <= hi) ? v.y : nf;
        float vx6 = (6 >= lo)            ? v.x : nf, vy6 = (6 >= lo) ? ((6 <= hi) ? v.y : nf) : nf;
        float vx7 = (7 <= hi && 7 >= lo) ? v.x : nf, vy7 = (7 <= hi && 7 >= lo) ? v.y : nf;
        vx6 = (6 <= hi) ? vx6 : nf;
        a0.x = fmaxf(a0.x, vx0); a0.y = fmaxf(a0.y, vy0);
        a1.x = fmaxf(a1.x, vx1); a1.y = fmaxf(a1.y, vy1);
        a2.x = fmaxf(a2.x, vx2); a2.y = fmaxf(a2.y, vy2);
        a3.x = fmaxf(a3.x, vx3); a3.y = fmaxf(a3.y, vy3);
        a4.x = fmaxf(a4.x, vx4); a4.y = fmaxf(a4.y, vy4);
        a5.x = fmaxf(a5.x, vx5); a5.y = fmaxf(a5.y, vy5);
        a6.x = fmaxf(a6.x, vx6); a6.y = fmaxf(a6.y, vy6);
        a7.x = fmaxf(a7.x, vx7); a7.y = fmaxf(a7.y, vy7);
        it = nx;
    }

    float2* dst2 = (float2*)(g_scratch + (((size_t)(b * WR + col)) << 12)) + g * 8 * 32 + lane;
    dst2[0 * 32] = a0; dst2[1 * 32] = a1; dst2[2 * 32] = a2; dst2[3 * 32] = a3;
    dst2[4 * 32] = a4; dst2[5 * 32] = a5; dst2[6 * 32] = a6; dst2[7 * 32] = a7;
}

// scratch [b][col][r][c] -> out [b][c][r][col], -inf -> 0, both sides 128-bit
__global__ void k_final(float* __restrict__ out) {
    __shared__ float tile[32][33];
    int z = blockIdx.z;
    int b = z >> 6;
    int r = z & 63;
    int col0 = blockIdx.x * 32;
    int c0   = blockIdx.y * 32;
    int tx = threadIdx.x;   // 0..7
    int ty = threadIdx.y;   // 0..31
    float4 f = *(const float4*)&g_scratch[(((size_t)(b * WR + col0 + ty)) << 12)
                                          + (r << 6) + c0 + tx * 4];
    tile[tx * 4 + 0][ty] = f.x;
    tile[tx * 4 + 1][ty] = f.y;
    tile[tx * 4 + 2][ty] = f.z;
    tile[tx * 4 + 3][ty] = f.w;
    __syncthreads();
    float4 w;
    w.x = tile[ty][tx * 4 + 0];
    w.y = tile[ty][tx * 4 + 1];
    w.z = tile[ty][tx * 4 + 2];
    w.w = tile[ty][tx * 4 + 3];
    if (w.x == -CUDART_INF_F) w.x = 0.0f;
    if (w.y == -CUDART_INF_F) w.y = 0.0f;
    if (w.z == -CUDART_INF_F) w.z = 0.0f;
    if (w.w == -CUDART_INF_F) w.w = 0.0f;
    *(float4*)&out[(((size_t)(b * NC + c0 + ty)) * HR + r) * WR + col0 + tx * 4] = w;
}

extern "C" void kernel_launch(void* const* d_in, const int* in_sizes, int n_in,
                              void* d_out, int out_size) {
    const float* feat = (const float*)d_in[0];   // [2,64,512,512] f32
    const int*   zbin = (const int*)d_in[1];     // [2,1,512,512] i32
    float*       out  = (float*)d_out;           // [2,64,64,2048] f32

    k_zero<<<(NBATCH * WR * NG + 255) / 256, 256>>>();
    k_geom<<<NB / 256, 256>>>();
    k_rowhi<<<(NBATCH * NB) / 256, 256>>>(zbin);
    k_transpose<<<dim3(NB / 32, NC / 32, NBATCH), dim3(8, 32)>>>(feat);
    k_project<<<dim3(WR, NBATCH), 256>>>();
    k_final<<<dim3(WR / 32, NC / 32, NBATCH * HR), dim3(8, 32)>>>(out);
}